// round 15
// baseline (speedup 1.0000x reference)
#include <cuda_runtime.h>
#include <cuda_fp16.h>
#include <math.h>

#define NN      50000
#define F_IN    512
#define F1      256
#define HEADS   8
#define HID     32
#define NCLASS  32
#define NEG_SLOPE 0.2f
#define ET_MAX  (800000 + NN)
#define CAP     128
#define SCAN_B  ((NN + 255) / 256)

// ---------------- scratch ----------------------------------------------------
__device__ __half g_h1 [(size_t)NN * F1];         // fp16 h1 (gather traffic /2)
__device__ float g_agg1[(size_t)NN * F1];
__device__ float g_h2  [(size_t)NN * NCLASS];
__device__ float g_W1r [(size_t)F_IN * F1];       // tf32-pre-rounded W1
__device__ float g_w1  [(size_t)HEADS * ET_MAX];  // fallback only
__device__ float g_w2  [(size_t)ET_MAX];          // fallback only
__device__ float g_ssrc1[NN * HEADS];
__device__ float g_sdst1[NN * HEADS];
__device__ float g_ssrc2[NN];
__device__ float g_sdst2[NN];
__device__ int g_deg   [NN];
__device__ int g_rowptr[NN + 1];
__device__ int g_cursor[NN];
__device__ int g_esrc  [ET_MAX];
__device__ int g_bsum  [256];
__device__ int g_boff  [256];

// ---------------- helpers ----------------------------------------------------
__device__ __forceinline__ float warp_allsum(float v) {
#pragma unroll
    for (int o = 16; o > 0; o >>= 1) v += __shfl_xor_sync(0xffffffffu, v, o);
    return v;
}
__device__ __forceinline__ float lrelu(float s) {
    return s > 0.f ? s : NEG_SLOPE * s;
}
__device__ __forceinline__ unsigned f2tf32(float f) {
    unsigned u;
    asm("cvt.rna.tf32.f32 %0, %1;" : "=r"(u) : "f"(f));
    return u;
}
__device__ __forceinline__ void mma_tf32(float* d, const unsigned* a, const unsigned* b) {
    asm volatile(
        "mma.sync.aligned.m16n8k8.row.col.f32.tf32.tf32.f32 "
        "{%0,%1,%2,%3}, {%4,%5,%6,%7}, {%8,%9}, {%0,%1,%2,%3};"
        : "+f"(d[0]), "+f"(d[1]), "+f"(d[2]), "+f"(d[3])
        : "r"(a[0]), "r"(a[1]), "r"(a[2]), "r"(a[3]), "r"(b[0]), "r"(b[1]));
}
__device__ __forceinline__ void cp_async16(void* smem, const void* gmem, int bytes) {
    unsigned s = (unsigned)__cvta_generic_to_shared(smem);
    asm volatile("cp.async.ca.shared.global [%0], [%1], 16, %2;"
                 :: "r"(s), "l"(gmem), "r"(bytes) : "memory");
}
#define CP_COMMIT() asm volatile("cp.async.commit_group;" ::: "memory")
#define CP_WAIT(n)  asm volatile("cp.async.wait_group %0;" :: "n"(n) : "memory")

// ---------------- W1 pre-round ----------------------------------------------
__global__ void w1round_kernel(const float* __restrict__ W1) {
    int i = blockIdx.x * blockDim.x + threadIdx.x;
    if (i < F_IN * F1) {
        unsigned u = f2tf32(W1[i]);
        g_W1r[i] = __uint_as_float(u);
    }
}

// ---------------- CSR build --------------------------------------------------
__global__ void deg_init_kernel() {
    int i = blockIdx.x * blockDim.x + threadIdx.x;
    if (i < NN) { g_deg[i] = 1; g_cursor[i] = 0; }
}
__global__ void deg_count_kernel(const int* __restrict__ ei, int E) {
    int e = blockIdx.x * blockDim.x + threadIdx.x;
    if (e < E) atomicAdd(&g_deg[ei[E + e]], 1);
}
__global__ void scan_p1() {
    __shared__ int sh[256];
    int b = blockIdx.x, t = threadIdx.x;
    int i = b * 256 + t;
    int d = (i < NN) ? g_deg[i] : 0;
    int v = d;
    sh[t] = v; __syncthreads();
#pragma unroll
    for (int off = 1; off < 256; off <<= 1) {
        int u = (t >= off) ? sh[t - off] : 0;
        __syncthreads();
        v += u; sh[t] = v;
        __syncthreads();
    }
    if (i < NN) g_rowptr[i] = v;
    if (t == 255) g_bsum[b] = v;
}
__global__ void scan_p2(int nb) {
    __shared__ int sh[256];
    int t = threadIdx.x;
    int d = (t < nb) ? g_bsum[t] : 0;
    int v = d;
    sh[t] = v; __syncthreads();
#pragma unroll
    for (int off = 1; off < 256; off <<= 1) {
        int u = (t >= off) ? sh[t - off] : 0;
        __syncthreads();
        v += u; sh[t] = v;
        __syncthreads();
    }
    g_boff[t] = v - d;
}
__global__ void scan_p3(int N) {
    int i = blockIdx.x * 256 + threadIdx.x;
    if (i < N) {
        int incl = g_rowptr[i] + g_boff[blockIdx.x];
        g_rowptr[i] = incl - g_deg[i];
        if (i == N - 1) g_rowptr[N] = incl;
    }
}
__global__ void fill_kernel(const int* __restrict__ ei, int E, int N) {
    int idx = blockIdx.x * blockDim.x + threadIdx.x;
    int ET = E + N;
    if (idx >= ET) return;
    int src, dst;
    if (idx < E) { src = ei[idx]; dst = ei[E + idx]; } else { src = dst = idx - E; }
    int pos = g_rowptr[dst] + atomicAdd(&g_cursor[dst], 1);
    g_esrc[pos] = src;
}

// ---------------- GEMM1 (tf32, 128x256x32, 3-stage, 512thr) + scores1 -------
// A fragments rounded rna (unbiased); B pre-rounded; h1 stored fp16.
#define A_PAD 36
#define B_PAD 264
#define AS_SZ (128 * A_PAD)
#define BS_SZ (32 * B_PAD)
#define GEMM1_SMEM ((3 * AS_SZ + 3 * BS_SZ) * 4)
__global__ void __launch_bounds__(512)
gemm1_kernel(const float* __restrict__ A,
             const float* __restrict__ asrc, const float* __restrict__ adst) {
    extern __shared__ float sm[];
    float (*As)[128][A_PAD] = reinterpret_cast<float(*)[128][A_PAD]>(sm);
    float (*Bs)[32][B_PAD]  = reinterpret_cast<float(*)[32][B_PAD]>(sm + 3 * AS_SZ);

    const int M = NN, K = F_IN;
    int tid  = threadIdx.x;
    int lane = tid & 31, wid = tid >> 5;
    int warp_m = wid >> 3, warp_n = wid & 7;
    int row0 = blockIdx.x * 128;
    int g = lane >> 2, tg = lane & 3;

    float acc[4][4][4];
#pragma unroll
    for (int i = 0; i < 4; i++)
#pragma unroll
        for (int j = 0; j < 4; j++)
#pragma unroll
            for (int r = 0; r < 4; r++) acc[i][j][r] = 0.f;

    int a_r = tid >> 2, a_c = (tid & 3) * 8;
    int b_r = tid >> 6, b_c = (tid & 63) * 4;
    int gr = row0 + a_r;
    const float* a_base = A + (size_t)min(gr, M - 1) * K + a_c;
    int a_bytes = (gr < M) ? 16 : 0;
    const float* b_base = g_W1r + (size_t)b_r * F1 + b_c;

    const int NT = K / 32;   // 16 k-tiles
#pragma unroll
    for (int s = 0; s < 2; s++) {
        int k0 = s * 32;
        cp_async16(&As[s][a_r][a_c],     a_base + k0,     a_bytes);
        cp_async16(&As[s][a_r][a_c + 4], a_base + k0 + 4, a_bytes);
#pragma unroll
        for (int rr = 0; rr < 4; rr++)
            cp_async16(&Bs[s][b_r + rr * 8][b_c],
                       b_base + (size_t)(k0 + rr * 8) * F1, 16);
        CP_COMMIT();
    }

    for (int kt = 0; kt < NT; kt++) {
        int buf = kt % 3;
        CP_WAIT(1);
        __syncthreads();
        if (kt + 2 < NT) {
            int nbuf = (kt + 2) % 3;
            int k2 = (kt + 2) * 32;
            cp_async16(&As[nbuf][a_r][a_c],     a_base + k2,     a_bytes);
            cp_async16(&As[nbuf][a_r][a_c + 4], a_base + k2 + 4, a_bytes);
#pragma unroll
            for (int rr = 0; rr < 4; rr++)
                cp_async16(&Bs[nbuf][b_r + rr * 8][b_c],
                           b_base + (size_t)(k2 + rr * 8) * F1, 16);
        }
        CP_COMMIT();

#pragma unroll
        for (int ks = 0; ks < 4; ks++) {
            int kb = ks * 8;
            unsigned bfr[4][2];
#pragma unroll
            for (int nt = 0; nt < 4; nt++) {
                int nb = warp_n * 32 + nt * 8 + g;
                bfr[nt][0] = __float_as_uint(Bs[buf][kb + tg    ][nb]);
                bfr[nt][1] = __float_as_uint(Bs[buf][kb + tg + 4][nb]);
            }
#pragma unroll
            for (int mt = 0; mt < 4; mt++) {
                int rb = warp_m * 64 + mt * 16;
                unsigned afr[4];
                afr[0] = f2tf32(As[buf][rb + g    ][kb + tg    ]);
                afr[1] = f2tf32(As[buf][rb + g + 8][kb + tg    ]);
                afr[2] = f2tf32(As[buf][rb + g    ][kb + tg + 4]);
                afr[3] = f2tf32(As[buf][rb + g + 8][kb + tg + 4]);
#pragma unroll
                for (int nt = 0; nt < 4; nt++)
                    mma_tf32(acc[mt][nt], afr, bfr[nt]);
            }
        }
    }

    // store h1 as fp16 (half2 per acc pair)
    __half2* h1v = reinterpret_cast<__half2*>(g_h1);
#pragma unroll
    for (int mt = 0; mt < 4; mt++) {
#pragma unroll
        for (int half = 0; half < 2; half++) {
            int grr = row0 + warp_m * 64 + mt * 16 + g + half * 8;
            if (grr >= M) continue;
#pragma unroll
            for (int nt = 0; nt < 4; nt++) {
                int gc = warp_n * 32 + nt * 8 + 2 * tg;
                h1v[((size_t)grr * F1 + gc) >> 1] =
                    __floats2half2_rn(acc[mt][nt][half * 2], acc[mt][nt][half * 2 + 1]);
            }
        }
    }

    // fused scores: warp covers exactly head = warp_n (fp32 accumulators)
    int head = warp_n;
    float as_[4][2], ad_[4][2];
#pragma unroll
    for (int nt = 0; nt < 4; nt++) {
        int cc = head * HID + nt * 8 + 2 * tg;
        as_[nt][0] = asrc[cc]; as_[nt][1] = asrc[cc + 1];
        ad_[nt][0] = adst[cc]; ad_[nt][1] = adst[cc + 1];
    }
#pragma unroll
    for (int mt = 0; mt < 4; mt++) {
#pragma unroll
        for (int half = 0; half < 2; half++) {
            float ps = 0.f, pd = 0.f;
#pragma unroll
            for (int nt = 0; nt < 4; nt++) {
                ps += acc[mt][nt][2*half] * as_[nt][0] + acc[mt][nt][2*half+1] * as_[nt][1];
                pd += acc[mt][nt][2*half] * ad_[nt][0] + acc[mt][nt][2*half+1] * ad_[nt][1];
            }
            ps += __shfl_xor_sync(0xffffffffu, ps, 1);
            ps += __shfl_xor_sync(0xffffffffu, ps, 2);
            pd += __shfl_xor_sync(0xffffffffu, pd, 1);
            pd += __shfl_xor_sync(0xffffffffu, pd, 2);
            int row = row0 + warp_m * 64 + mt * 16 + g + half * 8;
            if (row < M && tg == 0) {
                g_ssrc1[row * HEADS + head] = ps;
                g_sdst1[row * HEADS + head] = pd;
            }
        }
    }
}

// ---------------- layer-1 fused softmax + aggregate + ELU(+b1) --------------
// h1 gather is fp16 (half traffic)
__global__ void __launch_bounds__(256)
agg1_kernel(const float* __restrict__ b1) {
    __shared__ int   s_src[CAP];
    __shared__ float s_w[HEADS][CAP];
    int n = blockIdx.x;
    int tid = threadIdx.x, h = tid >> 5, lane = tid & 31;
    int r0 = g_rowptr[n], r1 = g_rowptr[n + 1], d = r1 - r0;
    float sdst = g_sdst1[n * HEADS + h];

    if (d <= CAP) {
        for (int p = tid; p < d; p += 256) s_src[p] = g_esrc[r0 + p];
        __syncthreads();
        float den = 0.f;
        for (int i = lane; i < d; i += 32) {
            int src = s_src[i];
            float w = __expf(lrelu(g_ssrc1[src * HEADS + h] + sdst));
            s_w[h][i] = w;
            den += w;
        }
        den = warp_allsum(den);
        float inv = __frcp_rn(den + 1e-16f);
        __syncwarp();
        float acc = 0.f;
#pragma unroll 8
        for (int i = 0; i < d; i++) {
            float a = s_w[h][i];
            int src = s_src[i];
            float hv = __half2float(g_h1[(size_t)src * F1 + h * HID + lane]);
            acc = fmaf(a, hv, acc);
        }
        acc *= inv;
        float v = acc + b1[h * HID + lane];
        g_agg1[(size_t)n * F1 + h * HID + lane] = v > 0.f ? v : expm1f(v);
    } else {
        float* w1h = g_w1 + (size_t)h * ET_MAX;
        float den = 0.f;
        for (int p = r0 + lane; p < r1; p += 32) {
            int src = g_esrc[p];
            float w = __expf(lrelu(g_ssrc1[src * HEADS + h] + sdst));
            w1h[p] = w; den += w;
        }
        den = warp_allsum(den);
        float inv = __frcp_rn(den + 1e-16f);
        __threadfence_block();
        __syncwarp();
        float acc = 0.f;
        for (int p = r0; p < r1; p++) {
            int src = g_esrc[p];
            float hv = __half2float(g_h1[(size_t)src * F1 + h * HID + lane]);
            acc = fmaf(w1h[p], hv, acc);
        }
        acc *= inv;
        float v = acc + b1[h * HID + lane];
        g_agg1[(size_t)n * F1 + h * HID + lane] = v > 0.f ? v : expm1f(v);
    }
}

// ---------------- GEMM2 (tf32, 128x32x16) + fused scores2 -------------------
__global__ void __launch_bounds__(256)
gemm2_kernel(const float* __restrict__ W2, const float* __restrict__ asrc,
             const float* __restrict__ adst) {
    __shared__ float As[2][128][20];
    __shared__ float Bs[2][16][36];

    const int M = NN, K = F1;
    int tid  = threadIdx.x;
    int lane = tid & 31, wid = tid >> 5;
    int row0 = blockIdx.x * 128;
    int g = lane >> 2, tg = lane & 3;

    float acc[4][4];
#pragma unroll
    for (int j = 0; j < 4; j++)
#pragma unroll
        for (int r = 0; r < 4; r++) acc[j][r] = 0.f;

    int a_r = tid >> 1, a_c = (tid & 1) * 8;
    int gr = row0 + a_r;
    const float* a_base = g_agg1 + (size_t)min(gr, M - 1) * K + a_c;
    int a_bytes = (gr < M) ? 16 : 0;
    int b_r = tid >> 3, b_c = (tid & 7) * 4;
    const float* b_base = W2 + (size_t)b_r * NCLASS + b_c;

    cp_async16(&As[0][a_r][a_c],     a_base,     a_bytes);
    cp_async16(&As[0][a_r][a_c + 4], a_base + 4, a_bytes);
    if (tid < 128) cp_async16(&Bs[0][b_r][b_c], b_base, 16);
    CP_COMMIT();

    const int NT = K / 16;
    for (int kt = 0; kt < NT; kt++) {
        int buf = kt & 1;
        if (kt + 1 < NT) {
            int k1 = (kt + 1) * 16;
            cp_async16(&As[buf ^ 1][a_r][a_c],     a_base + k1,     a_bytes);
            cp_async16(&As[buf ^ 1][a_r][a_c + 4], a_base + k1 + 4, a_bytes);
            if (tid < 128) cp_async16(&Bs[buf ^ 1][b_r][b_c],
                                      b_base + (size_t)k1 * NCLASS, 16);
            CP_COMMIT();
            CP_WAIT(1);
        } else {
            CP_WAIT(0);
        }
        __syncthreads();

#pragma unroll
        for (int ks = 0; ks < 2; ks++) {
            int kb = ks * 8;
            int rb = wid * 16;
            unsigned afr[4];
            afr[0] = f2tf32(As[buf][rb + g    ][kb + tg    ]);
            afr[1] = f2tf32(As[buf][rb + g + 8][kb + tg    ]);
            afr[2] = f2tf32(As[buf][rb + g    ][kb + tg + 4]);
            afr[3] = f2tf32(As[buf][rb + g + 8][kb + tg + 4]);
#pragma unroll
            for (int nt = 0; nt < 4; nt++) {
                int nb = nt * 8;
                unsigned bfr[2];
                bfr[0] = f2tf32(Bs[buf][kb + tg    ][nb + g]);
                bfr[1] = f2tf32(Bs[buf][kb + tg + 4][nb + g]);
                mma_tf32(acc[nt], afr, bfr);
            }
        }
        __syncthreads();
    }

    float as_[4][2], ad_[4][2];
#pragma unroll
    for (int nt = 0; nt < 4; nt++) {
        int cc = nt * 8 + 2 * tg;
        as_[nt][0] = asrc[cc]; as_[nt][1] = asrc[cc + 1];
        ad_[nt][0] = adst[cc]; ad_[nt][1] = adst[cc + 1];
    }
#pragma unroll
    for (int half = 0; half < 2; half++) {
        int row = row0 + wid * 16 + g + half * 8;
        float ps = 0.f, pd = 0.f;
#pragma unroll
        for (int nt = 0; nt < 4; nt++) {
            ps += acc[nt][2*half] * as_[nt][0] + acc[nt][2*half+1] * as_[nt][1];
            pd += acc[nt][2*half] * ad_[nt][0] + acc[nt][2*half+1] * ad_[nt][1];
        }
        ps += __shfl_xor_sync(0xffffffffu, ps, 1);
        ps += __shfl_xor_sync(0xffffffffu, ps, 2);
        pd += __shfl_xor_sync(0xffffffffu, pd, 1);
        pd += __shfl_xor_sync(0xffffffffu, pd, 2);
        if (row < M) {
#pragma unroll
            for (int nt = 0; nt < 4; nt++) {
                int gc = nt * 8 + 2 * tg;
                float2 v = make_float2(acc[nt][half * 2], acc[nt][half * 2 + 1]);
                *reinterpret_cast<float2*>(&g_h2[(size_t)row * NCLASS + gc]) = v;
            }
            if (tg == 0) { g_ssrc2[row] = ps; g_sdst2[row] = pd; }
        }
    }
}

// ---------------- layer-2 fused softmax + aggregate (+b2 + 1e-6) ------------
__global__ void __launch_bounds__(256)
agg2_kernel(const float* __restrict__ b2, float* __restrict__ out) {
    __shared__ int   s_src[8][CAP];
    __shared__ float s_w[8][CAP];
    int w = threadIdx.x >> 5, lane = threadIdx.x & 31;
    int n = blockIdx.x * 8 + w;
    if (n >= NN) return;
    int r0 = g_rowptr[n], r1 = g_rowptr[n + 1], d = r1 - r0;
    float sdst = g_sdst2[n];

    if (d <= CAP) {
        float den = 0.f;
        for (int i = lane; i < d; i += 32) {
            int src = g_esrc[r0 + i];
            s_src[w][i] = src;
            float wv = __expf(lrelu(g_ssrc2[src] + sdst));
            s_w[w][i] = wv;
            den += wv;
        }
        den = warp_allsum(den);
        float inv = __frcp_rn(den + 1e-16f);
        __syncwarp();
        float acc = 0.f;
#pragma unroll 8
        for (int i = 0; i < d; i++) {
            acc = fmaf(s_w[w][i], g_h2[(size_t)s_src[w][i] * NCLASS + lane], acc);
        }
        out[(size_t)n * NCLASS + lane] = acc * inv + b2[lane] + 1e-6f;
    } else {
        float den = 0.f;
        for (int p = r0 + lane; p < r1; p += 32) {
            int src = g_esrc[p];
            float wv = __expf(lrelu(g_ssrc2[src] + sdst));
            g_w2[p] = wv; den += wv;
        }
        den = warp_allsum(den);
        float inv = __frcp_rn(den + 1e-16f);
        __threadfence_block();
        __syncwarp();
        float acc = 0.f;
        for (int p = r0; p < r1; p++)
            acc = fmaf(g_w2[p], g_h2[(size_t)g_esrc[p] * NCLASS + lane], acc);
        out[(size_t)n * NCLASS + lane] = acc * inv + b2[lane] + 1e-6f;
    }
}

// ---------------- launch ----------------------------------------------------
extern "C" void kernel_launch(void* const* d_in, const int* in_sizes, int n_in,
                              void* d_out, int out_size) {
    const float* x     = (const float*)d_in[0];
    const int*   ei    = (const int*)d_in[1];
    const float* W1    = (const float*)d_in[2];
    const float* asrc1 = (const float*)d_in[3];
    const float* adst1 = (const float*)d_in[4];
    const float* b1    = (const float*)d_in[5];
    const float* W2    = (const float*)d_in[6];
    const float* asrc2 = (const float*)d_in[7];
    const float* adst2 = (const float*)d_in[8];
    const float* b2    = (const float*)d_in[9];
    float* out = (float*)d_out;

    int N  = in_sizes[0] / F_IN;   // 50000
    int E  = in_sizes[1] / 2;      // 800000
    int ET = E + N;

    cudaFuncSetAttribute(gemm1_kernel,
                         cudaFuncAttributeMaxDynamicSharedMemorySize, GEMM1_SMEM);

    cudaStream_t s2;
    cudaStreamCreateWithFlags(&s2, cudaStreamNonBlocking);
    cudaEvent_t ev0, ev1;
    cudaEventCreateWithFlags(&ev0, cudaEventDisableTiming);
    cudaEventCreateWithFlags(&ev1, cudaEventDisableTiming);

    cudaEventRecord(ev0, 0);
    cudaStreamWaitEvent(s2, ev0, 0);

    w1round_kernel<<<(F_IN * F1 + 255) / 256, 256>>>(W1);            // launch 1 (main)
    deg_init_kernel<<<SCAN_B, 256, 0, s2>>>();                       // launch 2
    deg_count_kernel<<<(E + 255) / 256, 256, 0, s2>>>(ei, E);        // launch 3

    gemm1_kernel<<<(N + 127) / 128, 512, GEMM1_SMEM>>>(              // launch 4 (profiled)
        x, asrc1, adst1);

    scan_p1<<<SCAN_B, 256, 0, s2>>>();
    scan_p2<<<1, 256, 0, s2>>>(SCAN_B);
    scan_p3<<<SCAN_B, 256, 0, s2>>>(N);
    fill_kernel<<<(ET + 255) / 256, 256, 0, s2>>>(ei, E, N);
    cudaEventRecord(ev1, s2);
    cudaStreamWaitEvent(0, ev1, 0);

    agg1_kernel<<<N, 256>>>(b1);
    gemm2_kernel<<<(N + 127) / 128, 256>>>(W2, asrc2, adst2);
    agg2_kernel<<<(N + 7) / 8, 256>>>(b2, out);
}

// round 16
// speedup vs baseline: 1.0313x; 1.0313x over previous
#include <cuda_runtime.h>
#include <cuda_fp16.h>
#include <math.h>

#define NN      50000
#define F_IN    512
#define F1      256
#define HEADS   8
#define HID     32
#define NCLASS  32
#define NEG_SLOPE 0.2f
#define ET_MAX  (800000 + NN)
#define CAP     128
#define SCAN_B  ((NN + 255) / 256)

// ---------------- scratch ----------------------------------------------------
__device__ __half g_h1 [(size_t)NN * F1];         // fp16 h1 (gather traffic /2)
__device__ float g_agg1[(size_t)NN * F1];
__device__ float g_h2  [(size_t)NN * NCLASS];
__device__ float g_W1r [(size_t)F_IN * F1];       // tf32-pre-rounded W1
__device__ float g_w1  [(size_t)HEADS * ET_MAX];  // fallback only
__device__ float g_w2  [(size_t)ET_MAX];          // fallback only
__device__ float g_ssrc1[NN * HEADS];
__device__ float g_sdst1[NN * HEADS];
__device__ float g_ssrc2[NN];
__device__ float g_sdst2[NN];
__device__ int g_deg   [NN];
__device__ int g_rowptr[NN + 1];
__device__ int g_cursor[NN];
__device__ int g_esrc  [ET_MAX];
__device__ int g_bsum  [256];
__device__ int g_boff  [256];

// ---------------- helpers ----------------------------------------------------
__device__ __forceinline__ float warp_allsum(float v) {
#pragma unroll
    for (int o = 16; o > 0; o >>= 1) v += __shfl_xor_sync(0xffffffffu, v, o);
    return v;
}
__device__ __forceinline__ float lrelu(float s) {
    return s > 0.f ? s : NEG_SLOPE * s;
}
__device__ __forceinline__ unsigned f2tf32(float f) {
    unsigned u;
    asm("cvt.rna.tf32.f32 %0, %1;" : "=r"(u) : "f"(f));
    return u;
}
__device__ __forceinline__ void mma_tf32(float* d, const unsigned* a, const unsigned* b) {
    asm volatile(
        "mma.sync.aligned.m16n8k8.row.col.f32.tf32.tf32.f32 "
        "{%0,%1,%2,%3}, {%4,%5,%6,%7}, {%8,%9}, {%0,%1,%2,%3};"
        : "+f"(d[0]), "+f"(d[1]), "+f"(d[2]), "+f"(d[3])
        : "r"(a[0]), "r"(a[1]), "r"(a[2]), "r"(a[3]), "r"(b[0]), "r"(b[1]));
}
__device__ __forceinline__ void cp_async16(void* smem, const void* gmem, int bytes) {
    unsigned s = (unsigned)__cvta_generic_to_shared(smem);
    asm volatile("cp.async.ca.shared.global [%0], [%1], 16, %2;"
                 :: "r"(s), "l"(gmem), "r"(bytes) : "memory");
}
#define CP_COMMIT() asm volatile("cp.async.commit_group;" ::: "memory")
#define CP_WAIT(n)  asm volatile("cp.async.wait_group %0;" :: "n"(n) : "memory")

// ---------------- W1 pre-round ----------------------------------------------
__global__ void w1round_kernel(const float* __restrict__ W1) {
    int i = blockIdx.x * blockDim.x + threadIdx.x;
    if (i < F_IN * F1) {
        unsigned u = f2tf32(W1[i]);
        g_W1r[i] = __uint_as_float(u);
    }
}

// ---------------- CSR build --------------------------------------------------
__global__ void deg_init_kernel() {
    int i = blockIdx.x * blockDim.x + threadIdx.x;
    if (i < NN) { g_deg[i] = 1; g_cursor[i] = 0; }
}
__global__ void deg_count_kernel(const int* __restrict__ ei, int E) {
    int e = blockIdx.x * blockDim.x + threadIdx.x;
    if (e < E) atomicAdd(&g_deg[ei[E + e]], 1);
}
__global__ void scan_p1() {
    __shared__ int sh[256];
    int b = blockIdx.x, t = threadIdx.x;
    int i = b * 256 + t;
    int d = (i < NN) ? g_deg[i] : 0;
    int v = d;
    sh[t] = v; __syncthreads();
#pragma unroll
    for (int off = 1; off < 256; off <<= 1) {
        int u = (t >= off) ? sh[t - off] : 0;
        __syncthreads();
        v += u; sh[t] = v;
        __syncthreads();
    }
    if (i < NN) g_rowptr[i] = v;
    if (t == 255) g_bsum[b] = v;
}
__global__ void scan_p2(int nb) {
    __shared__ int sh[256];
    int t = threadIdx.x;
    int d = (t < nb) ? g_bsum[t] : 0;
    int v = d;
    sh[t] = v; __syncthreads();
#pragma unroll
    for (int off = 1; off < 256; off <<= 1) {
        int u = (t >= off) ? sh[t - off] : 0;
        __syncthreads();
        v += u; sh[t] = v;
        __syncthreads();
    }
    g_boff[t] = v - d;
}
__global__ void scan_p3(int N) {
    int i = blockIdx.x * 256 + threadIdx.x;
    if (i < N) {
        int incl = g_rowptr[i] + g_boff[blockIdx.x];
        g_rowptr[i] = incl - g_deg[i];
        if (i == N - 1) g_rowptr[N] = incl;
    }
}
__global__ void fill_kernel(const int* __restrict__ ei, int E, int N) {
    int idx = blockIdx.x * blockDim.x + threadIdx.x;
    int ET = E + N;
    if (idx >= ET) return;
    int src, dst;
    if (idx < E) { src = ei[idx]; dst = ei[E + idx]; } else { src = dst = idx - E; }
    int pos = g_rowptr[dst] + atomicAdd(&g_cursor[dst], 1);
    g_esrc[pos] = src;
}

// ---------------- GEMM1 (tf32, 128x256x32, 3-stage, 512thr) + scores1 -------
// A fragments raw-bit (HW tf32 truncation); B pre-rounded; h1 stored fp16.
#define A_PAD 36
#define B_PAD 264
#define AS_SZ (128 * A_PAD)
#define BS_SZ (32 * B_PAD)
#define GEMM1_SMEM ((3 * AS_SZ + 3 * BS_SZ) * 4)
__global__ void __launch_bounds__(512)
gemm1_kernel(const float* __restrict__ A,
             const float* __restrict__ asrc, const float* __restrict__ adst) {
    extern __shared__ float sm[];
    float (*As)[128][A_PAD] = reinterpret_cast<float(*)[128][A_PAD]>(sm);
    float (*Bs)[32][B_PAD]  = reinterpret_cast<float(*)[32][B_PAD]>(sm + 3 * AS_SZ);

    const int M = NN, K = F_IN;
    int tid  = threadIdx.x;
    int lane = tid & 31, wid = tid >> 5;
    int warp_m = wid >> 3, warp_n = wid & 7;
    int row0 = blockIdx.x * 128;
    int g = lane >> 2, tg = lane & 3;

    float acc[4][4][4];
#pragma unroll
    for (int i = 0; i < 4; i++)
#pragma unroll
        for (int j = 0; j < 4; j++)
#pragma unroll
            for (int r = 0; r < 4; r++) acc[i][j][r] = 0.f;

    int a_r = tid >> 2, a_c = (tid & 3) * 8;
    int b_r = tid >> 6, b_c = (tid & 63) * 4;
    int gr = row0 + a_r;
    const float* a_base = A + (size_t)min(gr, M - 1) * K + a_c;
    int a_bytes = (gr < M) ? 16 : 0;
    const float* b_base = g_W1r + (size_t)b_r * F1 + b_c;

    const int NT = K / 32;   // 16 k-tiles
#pragma unroll
    for (int s = 0; s < 2; s++) {
        int k0 = s * 32;
        cp_async16(&As[s][a_r][a_c],     a_base + k0,     a_bytes);
        cp_async16(&As[s][a_r][a_c + 4], a_base + k0 + 4, a_bytes);
#pragma unroll
        for (int rr = 0; rr < 4; rr++)
            cp_async16(&Bs[s][b_r + rr * 8][b_c],
                       b_base + (size_t)(k0 + rr * 8) * F1, 16);
        CP_COMMIT();
    }

    for (int kt = 0; kt < NT; kt++) {
        int buf = kt % 3;
        CP_WAIT(1);
        __syncthreads();
        if (kt + 2 < NT) {
            int nbuf = (kt + 2) % 3;
            int k2 = (kt + 2) * 32;
            cp_async16(&As[nbuf][a_r][a_c],     a_base + k2,     a_bytes);
            cp_async16(&As[nbuf][a_r][a_c + 4], a_base + k2 + 4, a_bytes);
#pragma unroll
            for (int rr = 0; rr < 4; rr++)
                cp_async16(&Bs[nbuf][b_r + rr * 8][b_c],
                           b_base + (size_t)(k2 + rr * 8) * F1, 16);
        }
        CP_COMMIT();

#pragma unroll
        for (int ks = 0; ks < 4; ks++) {
            int kb = ks * 8;
            unsigned bfr[4][2];
#pragma unroll
            for (int nt = 0; nt < 4; nt++) {
                int nb = warp_n * 32 + nt * 8 + g;
                bfr[nt][0] = __float_as_uint(Bs[buf][kb + tg    ][nb]);
                bfr[nt][1] = __float_as_uint(Bs[buf][kb + tg + 4][nb]);
            }
#pragma unroll
            for (int mt = 0; mt < 4; mt++) {
                int rb = warp_m * 64 + mt * 16;
                unsigned afr[4];
                afr[0] = __float_as_uint(As[buf][rb + g    ][kb + tg    ]);
                afr[1] = __float_as_uint(As[buf][rb + g + 8][kb + tg    ]);
                afr[2] = __float_as_uint(As[buf][rb + g    ][kb + tg + 4]);
                afr[3] = __float_as_uint(As[buf][rb + g + 8][kb + tg + 4]);
#pragma unroll
                for (int nt = 0; nt < 4; nt++)
                    mma_tf32(acc[mt][nt], afr, bfr[nt]);
            }
        }
    }

    // store h1 as fp16 (half2 per acc pair)
    __half2* h1v = reinterpret_cast<__half2*>(g_h1);
#pragma unroll
    for (int mt = 0; mt < 4; mt++) {
#pragma unroll
        for (int half = 0; half < 2; half++) {
            int grr = row0 + warp_m * 64 + mt * 16 + g + half * 8;
            if (grr >= M) continue;
#pragma unroll
            for (int nt = 0; nt < 4; nt++) {
                int gc = warp_n * 32 + nt * 8 + 2 * tg;
                h1v[((size_t)grr * F1 + gc) >> 1] =
                    __floats2half2_rn(acc[mt][nt][half * 2], acc[mt][nt][half * 2 + 1]);
            }
        }
    }

    // fused scores: warp covers exactly head = warp_n (fp32 accumulators)
    int head = warp_n;
    float as_[4][2], ad_[4][2];
#pragma unroll
    for (int nt = 0; nt < 4; nt++) {
        int cc = head * HID + nt * 8 + 2 * tg;
        as_[nt][0] = asrc[cc]; as_[nt][1] = asrc[cc + 1];
        ad_[nt][0] = adst[cc]; ad_[nt][1] = adst[cc + 1];
    }
#pragma unroll
    for (int mt = 0; mt < 4; mt++) {
#pragma unroll
        for (int half = 0; half < 2; half++) {
            float ps = 0.f, pd = 0.f;
#pragma unroll
            for (int nt = 0; nt < 4; nt++) {
                ps += acc[mt][nt][2*half] * as_[nt][0] + acc[mt][nt][2*half+1] * as_[nt][1];
                pd += acc[mt][nt][2*half] * ad_[nt][0] + acc[mt][nt][2*half+1] * ad_[nt][1];
            }
            ps += __shfl_xor_sync(0xffffffffu, ps, 1);
            ps += __shfl_xor_sync(0xffffffffu, ps, 2);
            pd += __shfl_xor_sync(0xffffffffu, pd, 1);
            pd += __shfl_xor_sync(0xffffffffu, pd, 2);
            int row = row0 + warp_m * 64 + mt * 16 + g + half * 8;
            if (row < M && tg == 0) {
                g_ssrc1[row * HEADS + head] = ps;
                g_sdst1[row * HEADS + head] = pd;
            }
        }
    }
}

// ---------------- layer-1 fused softmax + aggregate + ELU(+b1) --------------
// h1 gather is fp16 (half traffic)
__global__ void __launch_bounds__(256)
agg1_kernel(const float* __restrict__ b1) {
    __shared__ int   s_src[CAP];
    __shared__ float s_w[HEADS][CAP];
    int n = blockIdx.x;
    int tid = threadIdx.x, h = tid >> 5, lane = tid & 31;
    int r0 = g_rowptr[n], r1 = g_rowptr[n + 1], d = r1 - r0;
    float sdst = g_sdst1[n * HEADS + h];

    if (d <= CAP) {
        for (int p = tid; p < d; p += 256) s_src[p] = g_esrc[r0 + p];
        __syncthreads();
        float den = 0.f;
        for (int i = lane; i < d; i += 32) {
            int src = s_src[i];
            float w = __expf(lrelu(g_ssrc1[src * HEADS + h] + sdst));
            s_w[h][i] = w;
            den += w;
        }
        den = warp_allsum(den);
        float inv = __frcp_rn(den + 1e-16f);
        __syncwarp();
        float acc = 0.f;
#pragma unroll 8
        for (int i = 0; i < d; i++) {
            float a = s_w[h][i];
            int src = s_src[i];
            float hv = __half2float(g_h1[(size_t)src * F1 + h * HID + lane]);
            acc = fmaf(a, hv, acc);
        }
        acc *= inv;
        float v = acc + b1[h * HID + lane];
        g_agg1[(size_t)n * F1 + h * HID + lane] = v > 0.f ? v : expm1f(v);
    } else {
        float* w1h = g_w1 + (size_t)h * ET_MAX;
        float den = 0.f;
        for (int p = r0 + lane; p < r1; p += 32) {
            int src = g_esrc[p];
            float w = __expf(lrelu(g_ssrc1[src * HEADS + h] + sdst));
            w1h[p] = w; den += w;
        }
        den = warp_allsum(den);
        float inv = __frcp_rn(den + 1e-16f);
        __threadfence_block();
        __syncwarp();
        float acc = 0.f;
        for (int p = r0; p < r1; p++) {
            int src = g_esrc[p];
            float hv = __half2float(g_h1[(size_t)src * F1 + h * HID + lane]);
            acc = fmaf(w1h[p], hv, acc);
        }
        acc *= inv;
        float v = acc + b1[h * HID + lane];
        g_agg1[(size_t)n * F1 + h * HID + lane] = v > 0.f ? v : expm1f(v);
    }
}

// ---------------- GEMM2 (tf32, 128x32x16) + fused scores2 -------------------
__global__ void __launch_bounds__(256)
gemm2_kernel(const float* __restrict__ W2, const float* __restrict__ asrc,
             const float* __restrict__ adst) {
    __shared__ float As[2][128][20];
    __shared__ float Bs[2][16][36];

    const int M = NN, K = F1;
    int tid  = threadIdx.x;
    int lane = tid & 31, wid = tid >> 5;
    int row0 = blockIdx.x * 128;
    int g = lane >> 2, tg = lane & 3;

    float acc[4][4];
#pragma unroll
    for (int j = 0; j < 4; j++)
#pragma unroll
        for (int r = 0; r < 4; r++) acc[j][r] = 0.f;

    int a_r = tid >> 1, a_c = (tid & 1) * 8;
    int gr = row0 + a_r;
    const float* a_base = g_agg1 + (size_t)min(gr, M - 1) * K + a_c;
    int a_bytes = (gr < M) ? 16 : 0;
    int b_r = tid >> 3, b_c = (tid & 7) * 4;
    const float* b_base = W2 + (size_t)b_r * NCLASS + b_c;

    cp_async16(&As[0][a_r][a_c],     a_base,     a_bytes);
    cp_async16(&As[0][a_r][a_c + 4], a_base + 4, a_bytes);
    if (tid < 128) cp_async16(&Bs[0][b_r][b_c], b_base, 16);
    CP_COMMIT();

    const int NT = K / 16;
    for (int kt = 0; kt < NT; kt++) {
        int buf = kt & 1;
        if (kt + 1 < NT) {
            int k1 = (kt + 1) * 16;
            cp_async16(&As[buf ^ 1][a_r][a_c],     a_base + k1,     a_bytes);
            cp_async16(&As[buf ^ 1][a_r][a_c + 4], a_base + k1 + 4, a_bytes);
            if (tid < 128) cp_async16(&Bs[buf ^ 1][b_r][b_c],
                                      b_base + (size_t)k1 * NCLASS, 16);
            CP_COMMIT();
            CP_WAIT(1);
        } else {
            CP_WAIT(0);
        }
        __syncthreads();

#pragma unroll
        for (int ks = 0; ks < 2; ks++) {
            int kb = ks * 8;
            int rb = wid * 16;
            unsigned afr[4];
            afr[0] = f2tf32(As[buf][rb + g    ][kb + tg    ]);
            afr[1] = f2tf32(As[buf][rb + g + 8][kb + tg    ]);
            afr[2] = f2tf32(As[buf][rb + g    ][kb + tg + 4]);
            afr[3] = f2tf32(As[buf][rb + g + 8][kb + tg + 4]);
#pragma unroll
            for (int nt = 0; nt < 4; nt++) {
                int nb = nt * 8;
                unsigned bfr[2];
                bfr[0] = f2tf32(Bs[buf][kb + tg    ][nb + g]);
                bfr[1] = f2tf32(Bs[buf][kb + tg + 4][nb + g]);
                mma_tf32(acc[nt], afr, bfr);
            }
        }
        __syncthreads();
    }

    float as_[4][2], ad_[4][2];
#pragma unroll
    for (int nt = 0; nt < 4; nt++) {
        int cc = nt * 8 + 2 * tg;
        as_[nt][0] = asrc[cc]; as_[nt][1] = asrc[cc + 1];
        ad_[nt][0] = adst[cc]; ad_[nt][1] = adst[cc + 1];
    }
#pragma unroll
    for (int half = 0; half < 2; half++) {
        int row = row0 + wid * 16 + g + half * 8;
        float ps = 0.f, pd = 0.f;
#pragma unroll
        for (int nt = 0; nt < 4; nt++) {
            ps += acc[nt][2*half] * as_[nt][0] + acc[nt][2*half+1] * as_[nt][1];
            pd += acc[nt][2*half] * ad_[nt][0] + acc[nt][2*half+1] * ad_[nt][1];
        }
        ps += __shfl_xor_sync(0xffffffffu, ps, 1);
        ps += __shfl_xor_sync(0xffffffffu, ps, 2);
        pd += __shfl_xor_sync(0xffffffffu, pd, 1);
        pd += __shfl_xor_sync(0xffffffffu, pd, 2);
        if (row < M) {
#pragma unroll
            for (int nt = 0; nt < 4; nt++) {
                int gc = nt * 8 + 2 * tg;
                float2 v = make_float2(acc[nt][half * 2], acc[nt][half * 2 + 1]);
                *reinterpret_cast<float2*>(&g_h2[(size_t)row * NCLASS + gc]) = v;
            }
            if (tg == 0) { g_ssrc2[row] = ps; g_sdst2[row] = pd; }
        }
    }
}

// ---------------- layer-2 fused softmax + aggregate (+b2 + 1e-6) ------------
__global__ void __launch_bounds__(256)
agg2_kernel(const float* __restrict__ b2, float* __restrict__ out) {
    __shared__ int   s_src[8][CAP];
    __shared__ float s_w[8][CAP];
    int w = threadIdx.x >> 5, lane = threadIdx.x & 31;
    int n = blockIdx.x * 8 + w;
    if (n >= NN) return;
    int r0 = g_rowptr[n], r1 = g_rowptr[n + 1], d = r1 - r0;
    float sdst = g_sdst2[n];

    if (d <= CAP) {
        float den = 0.f;
        for (int i = lane; i < d; i += 32) {
            int src = g_esrc[r0 + i];
            s_src[w][i] = src;
            float wv = __expf(lrelu(g_ssrc2[src] + sdst));
            s_w[w][i] = wv;
            den += wv;
        }
        den = warp_allsum(den);
        float inv = __frcp_rn(den + 1e-16f);
        __syncwarp();
        float acc = 0.f;
#pragma unroll 8
        for (int i = 0; i < d; i++) {
            acc = fmaf(s_w[w][i], g_h2[(size_t)s_src[w][i] * NCLASS + lane], acc);
        }
        out[(size_t)n * NCLASS + lane] = acc * inv + b2[lane] + 1e-6f;
    } else {
        float den = 0.f;
        for (int p = r0 + lane; p < r1; p += 32) {
            int src = g_esrc[p];
            float wv = __expf(lrelu(g_ssrc2[src] + sdst));
            g_w2[p] = wv; den += wv;
        }
        den = warp_allsum(den);
        float inv = __frcp_rn(den + 1e-16f);
        __threadfence_block();
        __syncwarp();
        float acc = 0.f;
        for (int p = r0; p < r1; p++)
            acc = fmaf(g_w2[p], g_h2[(size_t)g_esrc[p] * NCLASS + lane], acc);
        out[(size_t)n * NCLASS + lane] = acc * inv + b2[lane] + 1e-6f;
    }
}

// ---------------- launch ----------------------------------------------------
extern "C" void kernel_launch(void* const* d_in, const int* in_sizes, int n_in,
                              void* d_out, int out_size) {
    const float* x     = (const float*)d_in[0];
    const int*   ei    = (const int*)d_in[1];
    const float* W1    = (const float*)d_in[2];
    const float* asrc1 = (const float*)d_in[3];
    const float* adst1 = (const float*)d_in[4];
    const float* b1    = (const float*)d_in[5];
    const float* W2    = (const float*)d_in[6];
    const float* asrc2 = (const float*)d_in[7];
    const float* adst2 = (const float*)d_in[8];
    const float* b2    = (const float*)d_in[9];
    float* out = (float*)d_out;

    int N  = in_sizes[0] / F_IN;   // 50000
    int E  = in_sizes[1] / 2;      // 800000
    int ET = E + N;

    cudaFuncSetAttribute(gemm1_kernel,
                         cudaFuncAttributeMaxDynamicSharedMemorySize, GEMM1_SMEM);

    cudaStream_t s2;
    cudaStreamCreateWithFlags(&s2, cudaStreamNonBlocking);
    cudaEvent_t ev0, ev1;
    cudaEventCreateWithFlags(&ev0, cudaEventDisableTiming);
    cudaEventCreateWithFlags(&ev1, cudaEventDisableTiming);

    cudaEventRecord(ev0, 0);
    cudaStreamWaitEvent(s2, ev0, 0);

    w1round_kernel<<<(F_IN * F1 + 255) / 256, 256>>>(W1);            // launch 1 (main)
    deg_init_kernel<<<SCAN_B, 256, 0, s2>>>();                       // launch 2
    deg_count_kernel<<<(E + 255) / 256, 256, 0, s2>>>(ei, E);        // launch 3

    gemm1_kernel<<<(N + 127) / 128, 512, GEMM1_SMEM>>>(              // launch 4 (profiled)
        x, asrc1, adst1);

    scan_p1<<<SCAN_B, 256, 0, s2>>>();
    scan_p2<<<1, 256, 0, s2>>>(SCAN_B);
    scan_p3<<<SCAN_B, 256, 0, s2>>>(N);
    fill_kernel<<<(ET + 255) / 256, 256, 0, s2>>>(ei, E, N);
    cudaEventRecord(ev1, s2);
    cudaStreamWaitEvent(0, ev1, 0);

    agg1_kernel<<<N, 256>>>(b1);
    gemm2_kernel<<<(N + 127) / 128, 256>>>(W2, asrc2, adst2);
    agg2_kernel<<<(N + 7) / 8, 256>>>(b2, out);
}